// round 16
// baseline (speedup 1.0000x reference)
#include <cuda_runtime.h>
#include <cuda_bf16.h>
#include <math.h>
#include <stdint.h>

// Problem constants
#define BB 2
#define SS 2048
#define DD 1024
#define HH 16
#define HD 64
#define MTOT (BB*SS)       // 4096
#define NSLOTS 304         // 152 SMs x 2 CTAs (GB300)

// Scratch (allocation-free rule: __device__ globals)
__device__ float g_qkv[(size_t)BB*SS*3*DD];     // [B,S,3D] tf32 (V region unused)
__device__ float g_vT[(size_t)BB*SS*DD];        // [B][c][s] transposed V, tf32
__device__ float g_att[(size_t)BB*SS*DD];       // [B,S,D]  tf32-rounded
__device__ float g_wqkvT[(size_t)3*DD*DD];      // [3D, D]  tf32-rounded
__device__ float g_wprojT[(size_t)DD*DD];       // [D, D]   tf32-rounded
__device__ float g_xcvt[(size_t)MTOT*DD];       // [B,S,D]  tf32-rounded
// [0]=qkv tiles, [1]=attn tasks, [2]=proj tiles, [4],[5]=per-batch done
__device__ int   g_ctr[8];

// ===========================================================================
// helpers
// ===========================================================================
__device__ __forceinline__ uint32_t f2tf32(float f) {
    uint32_t u;
    asm("cvt.rna.tf32.f32 %0, %1;" : "=r"(u) : "f"(f));
    return u;
}
__device__ __forceinline__ float ex2f(float x) {
    float r;
    asm("ex2.approx.ftz.f32 %0, %1;" : "=f"(r) : "f"(x));
    return r;
}
__device__ __forceinline__ void mma_tf32(float* d, const uint32_t* a,
                                         const uint32_t* b) {
    asm volatile(
        "mma.sync.aligned.m16n8k8.row.col.f32.tf32.tf32.f32 "
        "{%0,%1,%2,%3}, {%4,%5,%6,%7}, {%8,%9}, {%0,%1,%2,%3};"
        : "+f"(d[0]), "+f"(d[1]), "+f"(d[2]), "+f"(d[3])
        : "r"(a[0]), "r"(a[1]), "r"(a[2]), "r"(a[3]), "r"(b[0]), "r"(b[1]));
}
__device__ __forceinline__ void ldsm_x4(uint32_t* r, uint32_t addr) {
    asm volatile(
        "ldmatrix.sync.aligned.m8n8.x4.shared.b16 {%0,%1,%2,%3}, [%4];"
        : "=r"(r[0]), "=r"(r[1]), "=r"(r[2]), "=r"(r[3]) : "r"(addr));
}
__device__ __forceinline__ uint32_t smem_u32(const void* p) {
    uint32_t a;
    asm("{ .reg .u64 t; cvta.to.shared.u64 t, %1; cvt.u32.u64 %0, t; }"
        : "=r"(a) : "l"(p));
    return a;
}
__device__ __forceinline__ void cp_async16(uint32_t dst, const void* src) {
    asm volatile("cp.async.cg.shared.global [%0], [%1], 16;"
                 :: "r"(dst), "l"(src));
}
__device__ __forceinline__ void cp_commit() {
    asm volatile("cp.async.commit_group;" ::: "memory");
}
template<int N> __device__ __forceinline__ void cp_wait() {
    asm volatile("cp.async.wait_group %0;" :: "n"(N) : "memory");
}

// ===========================================================================
// Merged prologue: x tf32-round (blocks 0..4095), weight transposes
// (blocks 4096..8191), counter reset (block 0).
// ===========================================================================
__global__ __launch_bounds__(256) void prep_kernel(
    const float* __restrict__ x, float* __restrict__ xcvt,
    const float* __restrict__ Wqkv, float* __restrict__ wqkvT,
    const float* __restrict__ Wproj, float* __restrict__ wprojT)
{
    __shared__ float t[32][33];
    int bid = blockIdx.x;
    if (bid == 0 && threadIdx.x < 8) g_ctr[threadIdx.x] = 0;

    if (bid < 4096) {
        size_t i = ((size_t)bid * 256 + threadIdx.x) * 4;
        float4 v = *(const float4*)&x[i];
        uint4 u;
        u.x = f2tf32(v.x); u.y = f2tf32(v.y);
        u.z = f2tf32(v.z); u.w = f2tf32(v.w);
        *(uint4*)&xcvt[i] = u;
    } else {
        int b2 = bid - 4096;
        int bx = b2 & 127;
        int by = b2 >> 7;
        const float* in;
        float* out;
        int C;
        if (bx < 96) { in = Wqkv;  out = wqkvT;  C = 3 * DD; }
        else         { bx -= 96; in = Wproj; out = wprojT; C = DD; }
        int x0 = bx * 32;
        int y0 = by * 32;
        int lx = threadIdx.x & 31, ly = threadIdx.x >> 5;
        #pragma unroll
        for (int j = 0; j < 4; j++) {
            int r = ly + j * 8;
            t[r][lx] = in[(size_t)(y0 + r) * C + x0 + lx];
        }
        __syncthreads();
        #pragma unroll
        for (int j = 0; j < 4; j++) {
            int a = ly + j * 8;
            out[(size_t)(x0 + a) * DD + y0 + lx] =
                __uint_as_float(f2tf32(t[lx][a]));
        }
    }
}

#define BK 32
#define NSTG 3
#define SWW4(r, w) (((r) << 5) + (((((w) >> 2) ^ ((r) & 7))) << 2))
#define VP  68
#define VT4(r, w) (((r) << 6) + (((((w) >> 2) ^ ((r) & 7))) << 2))

// ===========================================================================
// FUSED persistent QKV-GEMM + attention.
// Phase A: 768 QKV tiles, batch-0-first (tiles 0..383 are batch 0). V-region
//   tiles write transposed to vT. Each tile publishes to done[batch].
// Phase B: 512 attention tasks, batch-0-first, heavy-qt-first within batch;
//   each waits (tid0 spin) for done[batch]==384. By the time the QKV queue
//   drains (~2 tile-periods), batch 0 is complete -> tail CTAs flow straight
//   into attention, filling the QKV wave-quantization idle (~23us chip-time).
// ===========================================================================
__global__ __launch_bounds__(256, 2) void qkv_attn_kernel(
    const float* __restrict__ A, const float* __restrict__ Bt,
    const float* __restrict__ bias,
    float* __restrict__ qkv, float* __restrict__ vT,
    float* __restrict__ att)
{
    extern __shared__ uint32_t smu[];
    __shared__ int task_s;

    int tid = threadIdx.x;
    int w = tid >> 5, l = tid & 31;
    int g = l >> 2, t = l & 3;

    // ldmatrix lane geometry (both phases)
    int sel = l >> 3;
    int lr8 = l & 7;
    int arow_off = (sel & 1) * 8 + lr8;
    int awsel    = (sel >> 1) * 4;
    int brow_off = (sel >> 1) * 8 + lr8;
    int bwsel    = (sel & 1) * 4;

    // ---------------- Phase A: QKV projection ----------------
    {
        uint32_t* As = smu;                       // NSTG*128*BK
        uint32_t* Bs = As + NSTG * 128 * BK;
        float* bias_s = (float*)(Bs + NSTG * 128 * BK);

        int wm = w & 3;
        int wn = w >> 2;
        const int K = DD, N = 3 * DD;

        int lrow[4], lwoff[4], lc4[4];
        #pragma unroll
        for (int i = 0; i < 4; i++) {
            int u = tid + i * 256;
            int row = u >> 3;
            int c4  = u & 7;
            lrow[i] = row;
            lwoff[i] = (row << 5) + ((c4 ^ (row & 7)) << 2);
            lc4[i] = c4 * 4;
        }

        uint32_t sA = smem_u32(As);
        uint32_t sB = smem_u32(Bs);
        const uint32_t stg_bytes = 128 * BK * 4;

        for (;;) {
            if (tid == 0) task_s = atomicAdd(&g_ctr[0], 1);
            __syncthreads();
            int tl = task_s;
            if (tl >= 768) break;
            int bb = (tl >= 384) ? 1 : 0;             // batch-0 tiles first
            int ti = tl - bb * 384;
            int m0 = bb * 2048 + (ti / 24) * 128;
            int n0 = (ti % 24) * 128;

            if (tid < 128) bias_s[tid] = bias[n0 + tid];

            #pragma unroll
            for (int s = 0; s < NSTG - 1; s++) {
                int k0 = s * BK;
                #pragma unroll
                for (int i = 0; i < 4; i++) {
                    cp_async16(sA + s * stg_bytes + lwoff[i] * 4,
                               &A[(size_t)(m0 + lrow[i]) * K + k0 + lc4[i]]);
                    cp_async16(sB + s * stg_bytes + lwoff[i] * 4,
                               &Bt[(size_t)(n0 + lrow[i]) * K + k0 + lc4[i]]);
                }
                cp_commit();
            }

            float acc[2][8][4] = {};

            for (int c = 0; c < K / BK; c++) {
                cp_wait<NSTG - 2>();
                __syncthreads();

                int cn = c + NSTG - 1;
                if (cn < K / BK) {
                    int st = cn % NSTG;
                    int k0 = cn * BK;
                    #pragma unroll
                    for (int i = 0; i < 4; i++) {
                        cp_async16(sA + st * stg_bytes + lwoff[i] * 4,
                                   &A[(size_t)(m0 + lrow[i]) * K + k0
                                      + lc4[i]]);
                        cp_async16(sB + st * stg_bytes + lwoff[i] * 4,
                                   &Bt[(size_t)(n0 + lrow[i]) * K + k0
                                       + lc4[i]]);
                    }
                }
                cp_commit();

                uint32_t aBase = sA + (c % NSTG) * stg_bytes;
                uint32_t bBase = sB + (c % NSTG) * stg_bytes;
                #pragma unroll
                for (int ks = 0; ks < 4; ks++) {
                    uint32_t af[2][4];
                    #pragma unroll
                    for (int mt = 0; mt < 2; mt++) {
                        int row = wm * 32 + mt * 16 + arow_off;
                        ldsm_x4(af[mt], aBase + SWW4(row, 8 * ks + awsel) * 4);
                    }
                    uint32_t bf[4][4];
                    #pragma unroll
                    for (int ntp = 0; ntp < 4; ntp++) {
                        int row = wn * 64 + ntp * 16 + brow_off;
                        ldsm_x4(bf[ntp],
                                bBase + SWW4(row, 8 * ks + bwsel) * 4);
                    }
                    #pragma unroll
                    for (int mt = 0; mt < 2; mt++)
                        #pragma unroll
                        for (int ntp = 0; ntp < 4; ntp++) {
                            mma_tf32(acc[mt][2 * ntp],     af[mt],
                                     &bf[ntp][0]);
                            mma_tf32(acc[mt][2 * ntp + 1], af[mt],
                                     &bf[ntp][2]);
                        }
                }
            }

            bool vreg = (n0 >= 2 * DD);
            #pragma unroll
            for (int mt = 0; mt < 2; mt++) {
                int r0 = m0 + wm * 32 + mt * 16 + g;
                #pragma unroll
                for (int nt = 0; nt < 8; nt++) {
                    int cl = wn * 64 + nt * 8 + 2 * t;
                    int cc = n0 + cl;
                    float v00 = acc[mt][nt][0] + bias_s[cl];
                    float v01 = acc[mt][nt][1] + bias_s[cl + 1];
                    float v10 = acc[mt][nt][2] + bias_s[cl];
                    float v11 = acc[mt][nt][3] + bias_s[cl + 1];
                    if (vreg) {
                        int sx = r0 & (SS - 1);
                        int cv = cc - 2 * DD;
                        float* base = vT + (size_t)bb * SS * DD
                                         + (size_t)cv * SS + sx;
                        base[0]      = __uint_as_float(f2tf32(v00));
                        base[SS]     = __uint_as_float(f2tf32(v01));
                        base[8]      = __uint_as_float(f2tf32(v10));
                        base[SS + 8] = __uint_as_float(f2tf32(v11));
                    } else {
                        float2 v0, v1;
                        v0.x = __uint_as_float(f2tf32(v00));
                        v0.y = __uint_as_float(f2tf32(v01));
                        v1.x = __uint_as_float(f2tf32(v10));
                        v1.y = __uint_as_float(f2tf32(v11));
                        *(float2*)&qkv[(size_t)r0 * N + cc] = v0;
                        *(float2*)&qkv[(size_t)(r0 + 8) * N + cc] = v1;
                    }
                }
            }
            __threadfence();   // release this thread's stores
            __syncthreads();   // all threads fenced; smem reuse barrier
            if (tid == 0) atomicAdd(&g_ctr[4 + bb], 1);
        }
    }

    // ---------------- Phase B: attention ----------------
    {
        uint32_t* Qs = smu;                       // 128*VP (later: P)
        uint32_t* Kb = Qs + 128 * VP;             // 2 x 64*VP
        uint32_t* Vb = Kb + 2 * 64 * VP;          // 2 x 64*64 (transposed V)
        uint32_t sQ = smem_u32(Qs);
        uint32_t sK = smem_u32(Kb);
        uint32_t sV = smem_u32(Vb);
        const uint32_t kbuf_b = 64 * VP * 4;
        const uint32_t vbuf_b = 64 * 64 * 4;
        const size_t rs = 3 * DD;
        const float QSC = 0.125f * 1.44269504088896341f;
        const float* qkvc = g_qkv;   // read via the same symbol
        const float* vTc  = g_vT;

        int lr[4], lcc[4];
        #pragma unroll
        for (int i = 0; i < 4; i++) {
            int fid = tid + i * 256;
            lr[i]  = fid >> 4;
            lcc[i] = (fid & 15) << 2;
        }

        for (;;) {
            if (tid == 0) task_s = atomicAdd(&g_ctr[1], 1);
            __syncthreads();
            int task = task_s;
            if (task >= 512) return;
            int b = (task >= 256) ? 1 : 0;            // batch 0 first
            int idx = task & 255;
            int qt = 15 - (idx >> 4);                 // heavy tiles first
            int h = idx & 15;
            int qbase = qt * 128;
            int nkb = 2 * qt + 2;

            // dependency: all 384 QKV tiles of this batch complete
            if (tid == 0) {
                while (atomicAdd(&g_ctr[4 + b], 0) < 384) __nanosleep(100);
                __threadfence();
            }
            __syncthreads();

            const float* qp  = qkvc + ((size_t)b * SS + qbase) * rs + h * HD;
            const float* kp0 = qkvc + (size_t)b * SS * rs + DD + h * HD;
            const float* vp0 = vTc + (size_t)b * SS * DD
                                   + (size_t)(h * HD) * SS;

            // prologue: prefetch K/V block 0
            {
                #pragma unroll
                for (int i = 0; i < 4; i++) {
                    cp_async16(sK + (lr[i] * VP + lcc[i]) * 4,
                               kp0 + (size_t)lr[i] * rs + lcc[i]);
                    cp_async16(sV + VT4(lr[i], lcc[i]) * 4,
                               vp0 + (size_t)lr[i] * SS + lcc[i]);
                }
                cp_commit();
            }

            // load Q tile (scale folded, tf32)
            #pragma unroll
            for (int i = 0; i < 8; i++) {
                int fid = tid + i * 256;
                int r = fid >> 4;
                int c = (fid & 15) << 2;
                float4 q4 = *(const float4*)&qp[(size_t)r * rs + c];
                uint32_t* d = &Qs[r * VP + c];
                d[0] = f2tf32(q4.x * QSC);
                d[1] = f2tf32(q4.y * QSC);
                d[2] = f2tf32(q4.z * QSC);
                d[3] = f2tf32(q4.w * QSC);
            }
            __syncthreads();

            int rl0 = 16 * w + g;
            uint32_t aQ[8][4];
            #pragma unroll
            for (int kt = 0; kt < 8; kt++)
                ldsm_x4(aQ[kt],
                        sQ + ((16 * w + arow_off) * VP + 8 * kt + awsel) * 4);

            float O[8][4] = {};
            float l0 = 0.0f, l1 = 0.0f;
            int row0 = qbase + rl0;
            int row1 = row0 + 8;
            uint32_t* Pp = Qs;

            for (int kb = 0; kb < nkb; kb++) {
                cp_wait<0>();
                __syncthreads();

                if (kb + 1 < nkb) {
                    const float* kp = kp0 + (size_t)((kb + 1) * 64) * rs;
                    const float* vp = vp0 + (kb + 1) * 64;
                    uint32_t kDst = sK + ((kb + 1) & 1) * kbuf_b;
                    uint32_t vDst = sV + ((kb + 1) & 1) * vbuf_b;
                    #pragma unroll
                    for (int i = 0; i < 4; i++) {
                        cp_async16(kDst + (lr[i] * VP + lcc[i]) * 4,
                                   kp + (size_t)lr[i] * rs + lcc[i]);
                        cp_async16(vDst + VT4(lr[i], lcc[i]) * 4,
                                   vp + (size_t)lr[i] * SS + lcc[i]);
                    }
                }
                cp_commit();

                uint32_t kBase = sK + (kb & 1) * kbuf_b;
                uint32_t vBase = sV + (kb & 1) * vbuf_b;

                float s[8][4] = {};
                #pragma unroll
                for (int kt = 0; kt < 8; kt++) {
                    #pragma unroll
                    for (int ntp = 0; ntp < 4; ntp++) {
                        uint32_t kf[4];
                        ldsm_x4(kf, kBase +
                                ((ntp * 16 + brow_off) * VP + 8 * kt + bwsel)
                                * 4);
                        mma_tf32(s[2 * ntp],     aQ[kt], &kf[0]);
                        mma_tf32(s[2 * ntp + 1], aQ[kt], &kf[2]);
                    }
                }

                if (kb * 64 + 63 > row0) {
                    #pragma unroll
                    for (int nt = 0; nt < 8; nt++) {
                        int jg = kb * 64 + 8 * nt + 2 * t;
                        if (jg     > row0) s[nt][0] = -1e30f;
                        if (jg + 1 > row0) s[nt][1] = -1e30f;
                        if (jg     > row1) s[nt][2] = -1e30f;
                        if (jg + 1 > row1) s[nt][3] = -1e30f;
                    }
                }

                #pragma unroll
                for (int nt = 0; nt < 8; nt++) {
                    float p0 = ex2f(s[nt][0]);
                    float p1 = ex2f(s[nt][1]);
                    float p2 = ex2f(s[nt][2]);
                    float p3 = ex2f(s[nt][3]);
                    l0 += p0 + p1;
                    l1 += p2 + p3;
                    uint2 u0; u0.x = f2tf32(p0); u0.y = f2tf32(p1);
                    *(uint2*)&Pp[rl0 * VP + 8 * nt + 2 * t] = u0;
                    uint2 u1; u1.x = f2tf32(p2); u1.y = f2tf32(p3);
                    *(uint2*)&Pp[(rl0 + 8) * VP + 8 * nt + 2 * t] = u1;
                }
                __syncwarp();

                #pragma unroll
                for (int kt = 0; kt < 8; kt++) {
                    uint32_t aP[4];
                    ldsm_x4(aP, sQ +
                            ((16 * w + arow_off) * VP + 8 * kt + awsel) * 4);
                    #pragma unroll
                    for (int ntp = 0; ntp < 4; ntp++) {
                        uint32_t vf[4];
                        ldsm_x4(vf, vBase +
                                VT4(ntp * 16 + brow_off, 8 * kt + bwsel) * 4);
                        mma_tf32(O[2 * ntp],     aP, &vf[0]);
                        mma_tf32(O[2 * ntp + 1], aP, &vf[2]);
                    }
                }
            }

            l0 += __shfl_xor_sync(0xFFFFFFFF, l0, 1);
            l0 += __shfl_xor_sync(0xFFFFFFFF, l0, 2);
            l1 += __shfl_xor_sync(0xFFFFFFFF, l1, 1);
            l1 += __shfl_xor_sync(0xFFFFFFFF, l1, 2);
            float i0 = 1.0f / l0, i1 = 1.0f / l1;
            float* op = att + (size_t)b * SS * DD + h * HD;
            #pragma unroll
            for (int nt = 0; nt < 8; nt++) {
                int c = 8 * nt + 2 * t;
                float2 o0;
                o0.x = __uint_as_float(f2tf32(O[nt][0] * i0));
                o0.y = __uint_as_float(f2tf32(O[nt][1] * i0));
                *(float2*)&op[(size_t)row0 * DD + c] = o0;
                float2 o1;
                o1.x = __uint_as_float(f2tf32(O[nt][2] * i1));
                o1.y = __uint_as_float(f2tf32(O[nt][3] * i1));
                *(float2*)&op[(size_t)row1 * DD + c] = o1;
            }
            __syncthreads();   // Qs/task_s reuse barrier
        }
    }
}

// ===========================================================================
// Persistent tf32 mma.sync GEMM (output projection only).
// ===========================================================================
__global__ __launch_bounds__(256, 2) void gemm_mma_kernel(
    const float* __restrict__ A, const float* __restrict__ Bt,
    const float* __restrict__ bias, float* __restrict__ C,
    int M, int N, int K, int cid)
{
    __shared__ uint32_t As[NSTG][128 * BK];
    __shared__ uint32_t Bs[NSTG][128 * BK];
    __shared__ float    bias_s[128];
    __shared__ int      tile_s;

    int tid = threadIdx.x;
    int wid = tid >> 5;
    int lane = tid & 31;
    int wm = wid & 3;
    int wn = wid >> 2;
    int g = lane >> 2;
    int t = lane & 3;
    int nchunk = K / BK;
    int nbx = N >> 7;
    int ntiles = (M >> 7) * nbx;

    int sel = lane >> 3;
    int lr8 = lane & 7;
    int arow_off = (sel & 1) * 8 + lr8;
    int awsel    = (sel >> 1) * 4;
    int brow_off = (sel >> 1) * 8 + lr8;
    int bwsel    = (sel & 1) * 4;

    int lrow[4], lwoff[4], lc4[4];
    #pragma unroll
    for (int i = 0; i < 4; i++) {
        int u = tid + i * 256;
        int row = u >> 3;
        int c4  = u & 7;
        lrow[i] = row;
        lwoff[i] = (row << 5) + ((c4 ^ (row & 7)) << 2);
        lc4[i] = c4 * 4;
    }

    uint32_t sA = smem_u32(&As[0][0]);
    uint32_t sB = smem_u32(&Bs[0][0]);
    const uint32_t stg_bytes = 128 * BK * 4;

    for (;;) {
        if (tid == 0) tile_s = atomicAdd(&g_ctr[cid], 1);
        __syncthreads();
        int tile = tile_s;
        if (tile >= ntiles) return;
        int m0 = (tile / nbx) << 7;
        int n0 = (tile % nbx) << 7;

        if (tid < 128) bias_s[tid] = bias[n0 + tid];

        #pragma unroll
        for (int s = 0; s < NSTG - 1; s++) {
            int k0 = s * BK;
            #pragma unroll
            for (int i = 0; i < 4; i++) {
                cp_async16(sA + s * stg_bytes + lwoff[i] * 4,
                           &A[(size_t)(m0 + lrow[i]) * K + k0 + lc4[i]]);
                cp_async16(sB + s * stg_bytes + lwoff[i] * 4,
                           &Bt[(size_t)(n0 + lrow[i]) * K + k0 + lc4[i]]);
            }
            cp_commit();
        }

        float acc[2][8][4] = {};

        for (int c = 0; c < nchunk; c++) {
            cp_wait<NSTG - 2>();
            __syncthreads();

            int cn = c + NSTG - 1;
            if (cn < nchunk) {
                int st = cn % NSTG;
                int k0 = cn * BK;
                #pragma unroll
                for (int i = 0; i < 4; i++) {
                    cp_async16(sA + st * stg_bytes + lwoff[i] * 4,
                               &A[(size_t)(m0 + lrow[i]) * K + k0 + lc4[i]]);
                    cp_async16(sB + st * stg_bytes + lwoff[i] * 4,
                               &Bt[(size_t)(n0 + lrow[i]) * K + k0 + lc4[i]]);
                }
            }
            cp_commit();

            uint32_t aBase = sA + (c % NSTG) * stg_bytes;
            uint32_t bBase = sB + (c % NSTG) * stg_bytes;
            #pragma unroll
            for (int ks = 0; ks < 4; ks++) {
                uint32_t af[2][4];
                #pragma unroll
                for (int mt = 0; mt < 2; mt++) {
                    int row = wm * 32 + mt * 16 + arow_off;
                    ldsm_x4(af[mt], aBase + SWW4(row, 8 * ks + awsel) * 4);
                }
                uint32_t bf[4][4];
                #pragma unroll
                for (int ntp = 0; ntp < 4; ntp++) {
                    int row = wn * 64 + ntp * 16 + brow_off;
                    ldsm_x4(bf[ntp], bBase + SWW4(row, 8 * ks + bwsel) * 4);
                }
                #pragma unroll
                for (int mt = 0; mt < 2; mt++)
                    #pragma unroll
                    for (int ntp = 0; ntp < 4; ntp++) {
                        mma_tf32(acc[mt][2 * ntp],     af[mt], &bf[ntp][0]);
                        mma_tf32(acc[mt][2 * ntp + 1], af[mt], &bf[ntp][2]);
                    }
            }
        }

        #pragma unroll
        for (int mt = 0; mt < 2; mt++) {
            int r0 = m0 + wm * 32 + mt * 16 + g;
            #pragma unroll
            for (int nt = 0; nt < 8; nt++) {
                int cl = wn * 64 + nt * 8 + 2 * t;
                int cc = n0 + cl;
                float2 v0, v1;
                v0.x = acc[mt][nt][0] + bias_s[cl];
                v0.y = acc[mt][nt][1] + bias_s[cl + 1];
                v1.x = acc[mt][nt][2] + bias_s[cl];
                v1.y = acc[mt][nt][3] + bias_s[cl + 1];
                *(float2*)&C[(size_t)r0 * N + cc] = v0;
                *(float2*)&C[(size_t)(r0 + 8) * N + cc] = v1;
            }
        }
        __syncthreads();
    }
}

// ===========================================================================
// Launch
// ===========================================================================
extern "C" void kernel_launch(void* const* d_in, const int* in_sizes, int n_in,
                              void* d_out, int out_size)
{
    const float* x     = (const float*)d_in[0];
    const float* Wqkv  = (const float*)d_in[1];
    const float* bqkv  = (const float*)d_in[2];
    const float* Wproj = (const float*)d_in[3];
    const float* bproj = (const float*)d_in[4];
    float* out = (float*)d_out;

    float *qkv, *vT, *att, *wqkvT, *wprojT, *xcvt;
    cudaGetSymbolAddress((void**)&qkv, g_qkv);
    cudaGetSymbolAddress((void**)&vT, g_vT);
    cudaGetSymbolAddress((void**)&att, g_att);
    cudaGetSymbolAddress((void**)&wqkvT, g_wqkvT);
    cudaGetSymbolAddress((void**)&wprojT, g_wprojT);
    cudaGetSymbolAddress((void**)&xcvt, g_xcvt);

    // 0) merged prologue: x tf32-round + weight transposes + counter reset
    prep_kernel<<<8192, 256>>>(x, xcvt, Wqkv, wqkvT, Wproj, wprojT);

    // 1) fused QKV projection + attention (persistent, dep-counters)
    size_t smem_attn =
        (size_t)(128 * VP + 2 * 64 * VP + 2 * 64 * 64) * sizeof(uint32_t);
    size_t smem_gemm =
        (size_t)(2 * NSTG * 128 * BK + 128) * sizeof(uint32_t);
    size_t smem_fused = smem_attn > smem_gemm ? smem_attn : smem_gemm;
    cudaFuncSetAttribute(qkv_attn_kernel,
                         cudaFuncAttributeMaxDynamicSharedMemorySize,
                         (int)smem_fused);
    qkv_attn_kernel<<<NSLOTS, 256, smem_fused>>>(
        xcvt, wqkvT, bqkv, qkv, vT, att);

    // 2) output projection (persistent), fp32 output
    gemm_mma_kernel<<<NSLOTS, 256>>>(
        att, wprojT, bproj, out, MTOT, DD, DD, 2);
}